// round 14
// baseline (speedup 1.0000x reference)
#include <cuda_runtime.h>
#include <cuda_bf16.h>
#include <cstdint>

// MixedEmbeddingV2: out[b,s,:] = emb_weight[x[b,s], :] * col_scale[:]
// col_scale: 4-segment step function (192-col segments, suffix sums of weights).
//
// R3/R5 post-mortem: dur pinned at 14.8us across 1.75x in-flight-load swing and
// 46->75% occupancy; L2 pinned at 34.0% = ~6300 B/cyc achieved LTS cap (~34% of
// ncu's theoretical peak). Model: chip L2-bandwidth floor on 100 MB of traffic.
// This round: discriminating experiment — cp.async deep pipeline (5 stages in
// flight, ~180 KB gather bytes in flight per SM, no barriers in steady loop).
// If dur stays ~14.8 -> LTS floor confirmed. If latency-bound -> ~10-11.5us.

#define MAX_D        768
#define VEC          (MAX_D / 4)    // 192 float4 per row
#define THREADS      192
#define TPS          2              // tokens per pipeline stage
#define STAGES       6              // smem ring buffers
#define PRE          5              // stages in flight ahead (PRE+1 <= STAGES)
#define TOK_PER_CTA  16
#define NSTAGE       (TOK_PER_CTA / TPS)   // 8
#define VOCAB        50257

__global__ __launch_bounds__(THREADS)
void mixed_embedding_pipe(const int* __restrict__ x,
                          const float* __restrict__ weights,
                          const float4* __restrict__ emb,   // [VOCAB, 192] float4
                          float4* __restrict__ out,         // [N_TOK, 192] float4
                          int n_tok)
{
    __shared__ float4 buf[STAGES][TPS][VEC];   // 6*2*192*16 = 36864 B
    __shared__ int    ids_s[TOK_PER_CTA];

    const int tid  = threadIdx.x;              // 0..191
    const int base = blockIdx.x * TOK_PER_CTA;

    // Stage the 16 token ids once (clamped: crash-proof).
    if (tid < TOK_PER_CTA) {
        int t  = base + tid;
        int id = (t < n_tok) ? x[t] : 0;
        id = (id < 0) ? 0 : ((id >= VOCAB) ? VOCAB - 1 : id);
        ids_s[tid] = id;
    }

    // Per-thread column scale: suffix sums of the 4 weights.
    const float w0 = __ldg(weights + 0);
    const float w1 = __ldg(weights + 1);
    const float w2 = __ldg(weights + 2);
    const float w3 = __ldg(weights + 3);
    const float s3 = w3;
    const float s2 = w2 + s3;
    const float s1 = w1 + s2;
    const float s0 = w0 + s1;
    const int   seg   = tid / 48;              // 48 float4 per 192-col segment
    const float scale = (seg == 0) ? s0 : (seg == 1) ? s1 : (seg == 2) ? s2 : s3;

    __syncthreads();                           // ids_s visible to all

    // Issue one stage: TPS rows gathered via cp.async.cg (16B per thread).
    auto issue_stage = [&](int s) {
        int slot = s % STAGES;
#pragma unroll
        for (int t = 0; t < TPS; t++) {
            int row = ids_s[s * TPS + t];
            const float4* src = emb + (size_t)row * VEC + tid;
            unsigned smem_addr =
                (unsigned)__cvta_generic_to_shared(&buf[slot][t][tid]);
            asm volatile("cp.async.cg.shared.global [%0], [%1], 16;\n"
                         :: "r"(smem_addr), "l"(src) : "memory");
        }
        asm volatile("cp.async.commit_group;\n" ::: "memory");
    };

    // Prologue: fill PRE stages.
#pragma unroll
    for (int s = 0; s < PRE; s++) issue_stage(s);

    // Steady loop: keep exactly PRE+1 groups pending (empty commits in tail so
    // wait_group<PRE> always retires the oldest real group).
    for (int s = 0; s < NSTAGE; s++) {
        if (s + PRE < NSTAGE) {
            issue_stage(s + PRE);
        } else {
            asm volatile("cp.async.commit_group;\n" ::: "memory");
        }
        asm volatile("cp.async.wait_group %0;\n" :: "n"(PRE) : "memory");
        // Each thread consumes exactly the smem bytes it copied -> no barrier.
        int slot = s % STAGES;
#pragma unroll
        for (int t = 0; t < TPS; t++) {
            float4 v = buf[slot][t][tid];
            float4 r;
            r.x = v.x * scale;
            r.y = v.y * scale;
            r.z = v.z * scale;
            r.w = v.w * scale;
            int tok = base + s * TPS + t;
            if (tok < n_tok)
                out[(size_t)tok * VEC + tid] = r;
        }
    }
}

extern "C" void kernel_launch(void* const* d_in, const int* in_sizes, int n_in,
                              void* d_out, int out_size)
{
    // metadata order: x (int32, B*S), weights (f32, 4), emb_weight (f32, VOCAB*768)
    const int* x         = (const int*)d_in[0];
    const float* weights = (const float*)d_in[1];
    const float4* emb    = (const float4*)d_in[2];
    float4* out          = (float4*)d_out;

    const int n_tok = in_sizes[0];                              // 16384
    const int grid  = (n_tok + TOK_PER_CTA - 1) / TOK_PER_CTA;  // 1024

    mixed_embedding_pipe<<<grid, THREADS>>>(x, weights, emb, out, n_tok);
}